// round 17
// baseline (speedup 1.0000x reference)
#include <cuda_runtime.h>
#include <cuda_bf16.h>
#include <math.h>
#include <stdint.h>

#define NB 4
#define NH 16
#define NS 1024
#define ND 64

#define QHS 68      // q packed tile stride (words), mod 32 == 4
#define KHS 68      // k tile stride (words), mod 32 == 4
#define VSS 72      // v tile stride, mod 32 == 8
#define EBS 68      // e tile stride (kernel B), mod 32 == 4

// Kernel A geometry
#define ATQ 128
#define ATK 64
#define ANT 256
#define ANTILES (NS / ATK)

// Kernel B geometry
#define BTQ 128
#define BTK 64
#define BNT 256
#define BNTILES (NS / BTK)

// Precomputed, head-independent tables + scratch.
__device__ float    g_resc[NB * NS * NS];        // (1+e)/(1+exp(1-dist))
__device__ float    g_madj[NB * NS * NS];        // mask ? adj : -1e9
__device__ uint32_t g_qhl[NB * NH * NS * ND];    // q/8 packed bf16 hi|lo
__device__ uint32_t g_khl[NB * NH * NS * ND];    // k packed bf16 hi|lo
__device__ float    g_vtf[NB * NH * NS * ND];    // tf32(v) bits
__device__ float    g_rinv[NB * NH * NS];        // 1 / row sums

__device__ __forceinline__ uint32_t f2tf(float f) {
    uint32_t r;
    asm("cvt.rna.tf32.f32 %0, %1;" : "=r"(r) : "f"(f));
    return r;
}
__device__ __forceinline__ uint32_t pack_bf16x2_split(float f) {
    __nv_bfloat16 h = __float2bfloat16(f);
    float resid = f - __bfloat162float(h);
    __nv_bfloat16 l = __float2bfloat16(resid);
    return (uint32_t)__bfloat16_as_ushort(h) |
           ((uint32_t)__bfloat16_as_ushort(l) << 16);
}

#define PREP_TBL_BLOCKS ((NB * NS * NS) / 1024)          // 4096
#define PREP_QKV_BLOCKS ((NB * NH * NS * ND) / 1024)     // 4096

__global__ void prep_all_kernel(const float* __restrict__ dist,
                                const float* __restrict__ adj,
                                const int*   __restrict__ mask,
                                const float* __restrict__ q,
                                const float* __restrict__ k,
                                const float* __restrict__ v) {
    int bid = blockIdx.x;
    if (bid < PREP_TBL_BLOCKS) {
        int i = (bid * 256 + threadIdx.x) * 4;
        int b = i >> 20;
        int j = i & (NS - 1);
        float4 d = *(const float4*)(dist + i);
        float4 a = *(const float4*)(adj + i);
        int4   m = *(const int4*)(mask + b * NS + j);
        float4 r;
        r.x = 3.7182817f / (1.0f + __expf(1.0f - d.x));
        r.y = 3.7182817f / (1.0f + __expf(1.0f - d.y));
        r.z = 3.7182817f / (1.0f + __expf(1.0f - d.z));
        r.w = 3.7182817f / (1.0f + __expf(1.0f - d.w));
        *(float4*)(g_resc + i) = r;
        float4 ma;
        ma.x = (m.x == 0) ? -1.0e9f : a.x;
        ma.y = (m.y == 0) ? -1.0e9f : a.y;
        ma.z = (m.z == 0) ? -1.0e9f : a.z;
        ma.w = (m.w == 0) ? -1.0e9f : a.w;
        *(float4*)(g_madj + i) = ma;
    } else {
        int i = ((bid - PREP_TBL_BLOCKS) * 256 + threadIdx.x) * 4;
        float4 qv = *(const float4*)(q + i);
        float4 kv = *(const float4*)(k + i);
        float4 vv = *(const float4*)(v + i);
        uint4 qo, ko;
        float4 vo;
        qo.x = pack_bf16x2_split(qv.x * 0.125f);
        qo.y = pack_bf16x2_split(qv.y * 0.125f);
        qo.z = pack_bf16x2_split(qv.z * 0.125f);
        qo.w = pack_bf16x2_split(qv.w * 0.125f);
        ko.x = pack_bf16x2_split(kv.x);
        ko.y = pack_bf16x2_split(kv.y);
        ko.z = pack_bf16x2_split(kv.z);
        ko.w = pack_bf16x2_split(kv.w);
        vo.x = __uint_as_float(f2tf(vv.x));
        vo.y = __uint_as_float(f2tf(vv.y));
        vo.z = __uint_as_float(f2tf(vv.z));
        vo.w = __uint_as_float(f2tf(vv.w));
        *(uint4*)(g_qhl + i) = qo;
        *(uint4*)(g_khl + i) = ko;
        *(float4*)(g_vtf + i) = vo;
    }
}

__device__ __forceinline__ void mma_bf16(float* c,
                                         uint32_t a0, uint32_t a1, uint32_t a2, uint32_t a3,
                                         uint32_t b0, uint32_t b1) {
    asm volatile("mma.sync.aligned.m16n8k16.row.col.f32.bf16.bf16.f32 "
                 "{%0,%1,%2,%3}, {%4,%5,%6,%7}, {%8,%9}, {%0,%1,%2,%3};"
                 : "+f"(c[0]), "+f"(c[1]), "+f"(c[2]), "+f"(c[3])
                 : "r"(a0), "r"(a1), "r"(a2), "r"(a3), "r"(b0), "r"(b1));
}
__device__ __forceinline__ void mma_tf32(float* c,
                                         uint32_t a0, uint32_t a1, uint32_t a2, uint32_t a3,
                                         uint32_t b0, uint32_t b1) {
    asm volatile("mma.sync.aligned.m16n8k8.row.col.f32.tf32.tf32.f32 "
                 "{%0,%1,%2,%3}, {%4,%5,%6,%7}, {%8,%9}, {%0,%1,%2,%3};"
                 : "+f"(c[0]), "+f"(c[1]), "+f"(c[2]), "+f"(c[3])
                 : "r"(a0), "r"(a1), "r"(a2), "r"(a3), "r"(b0), "r"(b1));
}

__device__ __forceinline__ void cp_async16(void* smem_dst, const void* gsrc) {
    uint32_t sa = (uint32_t)__cvta_generic_to_shared(smem_dst);
    asm volatile("cp.async.cg.shared.global [%0], [%1], 16;" :: "r"(sa), "l"(gsrc));
}
#define CP_COMMIT()  asm volatile("cp.async.commit_group;")
#define CP_WAIT(n)   asm volatile("cp.async.wait_group %0;" :: "n"(n))

// ==== Kernel A: scores -> unnormalized e (tf32 bits), TQ=128, occ 2 ====
__global__ __launch_bounds__(ANT, 2)
void score_kernel(float* __restrict__ attn_out) {
    extern __shared__ float smem[];
    uint32_t* qhl_s = (uint32_t*)smem;                   // ATQ*QHS   (8704 w)
    uint32_t* kbuf  = (uint32_t*)(smem + ATQ * QHS);     // 2*ATK*KHS (8704 w)

    const int tid  = threadIdx.x;
    const int wid  = tid >> 5;    // 0..7 (m16 group within TQ=128)
    const int lane = tid & 31;
    const int g    = lane >> 2;
    const int tg   = lane & 3;

    const int q0 = blockIdx.x * ATQ;
    const int h  = blockIdx.y;
    const int b  = blockIdx.z;
    const size_t bh = (size_t)b * NH + h;

    const uint32_t* qg  = g_qhl + (bh * NS + q0) * ND;
    const uint32_t* khg = g_khl + bh * NS * ND;
    float* eg = attn_out + (bh * NS + q0) * NS;

    // ---- prologue: q + k0 (group 0), k1 (group 1) ----
    for (int i = tid; i < ATQ * 16; i += ANT) {
        int r = i >> 4, c = (i & 15) << 2;
        cp_async16(qhl_s + r * QHS + c, qg + (size_t)r * ND + c);
    }
    for (int i = tid; i < ATK * 16; i += ANT) {
        int r = i >> 4, c = (i & 15) << 2;
        cp_async16(kbuf + r * KHS + c, khg + (size_t)r * ND + c);
    }
    CP_COMMIT();
    for (int i = tid; i < ATK * 16; i += ANT) {
        int r = i >> 4, c = (i & 15) << 2;
        cp_async16(kbuf + ATK * KHS + r * KHS + c, khg + (size_t)(ATK + r) * ND + c);
    }
    CP_COMMIT();
    CP_WAIT(1);
    __syncthreads();

    // ---- A fragments (m16 slice of q) -> packed regs ----
    uint32_t apk[8][4];
    const int r_lo = wid * 16 + g;
    #pragma unroll
    for (int ks = 0; ks < 8; ks++) {
        int col = ks * 8 + tg;
        apk[ks][0] = qhl_s[r_lo * QHS + col];
        apk[ks][1] = qhl_s[(r_lo + 8) * QHS + col];
        apk[ks][2] = qhl_s[r_lo * QHS + col + 4];
        apk[ks][3] = qhl_s[(r_lo + 8) * QHS + col + 4];
    }

    float rs0 = 0.0f, rs1 = 0.0f;
    const float* rbase = g_resc + ((size_t)b * NS + q0 + r_lo) * NS;
    const float* abase = g_madj + ((size_t)b * NS + q0 + r_lo) * NS;

    for (int kt = 0; kt < ANTILES; kt++) {
        if (kt < ANTILES - 1) { CP_WAIT(1); } else { CP_WAIT(0); }
        __syncthreads();

        const uint32_t* kw = kbuf + (kt & 1) * ATK * KHS;

        float c4[8][4];
        #pragma unroll
        for (int nt = 0; nt < 8; nt++)
            #pragma unroll
            for (int j = 0; j < 4; j++) c4[nt][j] = 0.0f;

        #pragma unroll
        for (int ks = 0; ks < 8; ks++) {
            int col = ks * 8 + tg;
            uint32_t p0 = apk[ks][0], p1 = apk[ks][1];
            uint32_t p2 = apk[ks][2], p3 = apk[ks][3];
            uint32_t hh0 = __byte_perm(p0, p0, 0x1010);
            uint32_t hh1 = __byte_perm(p1, p1, 0x1010);
            uint32_t hh2 = __byte_perm(p2, p2, 0x1010);
            uint32_t hh3 = __byte_perm(p3, p3, 0x1010);
            uint32_t ll0 = __byte_perm(p0, p0, 0x3232);
            uint32_t ll1 = __byte_perm(p1, p1, 0x3232);
            uint32_t ll2 = __byte_perm(p2, p2, 0x3232);
            uint32_t ll3 = __byte_perm(p3, p3, 0x3232);
            #pragma unroll
            for (int nt = 0; nt < 8; nt++) {
                uint32_t bp0 = kw[(nt * 8 + g) * KHS + col];
                uint32_t bp1 = kw[(nt * 8 + g) * KHS + col + 4];
                mma_bf16(c4[nt], hh0, hh1, hh2, hh3, bp0, bp1);
                mma_bf16(c4[nt], ll0, ll1, ll2, ll3, bp0, bp1);
            }
        }

        // epilogue: e = exp(relu(s)*resc + madj); row sums; store tf32(e)
        #pragma unroll
        for (int nt = 0; nt < 8; nt++) {
            int kc = kt * ATK + nt * 8 + 2 * tg;
            float2 rl = *(const float2*)(rbase + kc);
            float2 al = *(const float2*)(abase + kc);
            float2 rh = *(const float2*)(rbase + 8 * NS + kc);
            float2 ah = *(const float2*)(abase + 8 * NS + kc);
            float e00 = __expf(fmaxf(c4[nt][0], 0.0f) * rl.x + al.x);
            float e01 = __expf(fmaxf(c4[nt][1], 0.0f) * rl.y + al.y);
            float e10 = __expf(fmaxf(c4[nt][2], 0.0f) * rh.x + ah.x);
            float e11 = __expf(fmaxf(c4[nt][3], 0.0f) * rh.y + ah.y);
            rs0 += e00 + e01;
            rs1 += e10 + e11;
            float2 t0 = make_float2(__uint_as_float(f2tf(e00)), __uint_as_float(f2tf(e01)));
            float2 t1 = make_float2(__uint_as_float(f2tf(e10)), __uint_as_float(f2tf(e11)));
            __stcs((float2*)(eg + (size_t)r_lo * NS + kc), t0);
            __stcs((float2*)(eg + (size_t)(r_lo + 8) * NS + kc), t1);
        }
        __syncthreads();

        if (kt + 2 < ANTILES) {
            uint32_t* dst = kbuf + (kt & 1) * ATK * KHS;
            for (int i = tid; i < ATK * 16; i += ANT) {
                int r = i >> 4, c = (i & 15) << 2;
                cp_async16(dst + r * KHS + c,
                           khg + (size_t)((kt + 2) * ATK + r) * ND + c);
            }
            CP_COMMIT();
        }
    }

    // row sums: each warp owns its full rows -> quad reduce, direct store
    rs0 += __shfl_xor_sync(0xffffffffu, rs0, 1);
    rs0 += __shfl_xor_sync(0xffffffffu, rs0, 2);
    rs1 += __shfl_xor_sync(0xffffffffu, rs1, 1);
    rs1 += __shfl_xor_sync(0xffffffffu, rs1, 2);
    if (tg == 0) {
        g_rinv[bh * NS + q0 + r_lo] = 1.0f / rs0;
        g_rinv[bh * NS + q0 + r_lo + 8] = 1.0f / rs1;
    }
}

// ==== Kernel B: normalize attn + out = P @ V, TQ=128, warp-per-m16 full k ====
__global__ __launch_bounds__(BNT, 2)
void pv_kernel(float* __restrict__ out,
               float* __restrict__ attn) {
    extern __shared__ float smem[];
    float* ebuf   = smem;                              // 2*BTQ*EBS (17408 w)
    float* vbuf   = ebuf + 2 * BTQ * EBS;              // 2*BTK*VSS (9216 w)
    float* rinv_s = vbuf + 2 * BTK * VSS;              // 128

    const int tid  = threadIdx.x;
    const int wid  = tid >> 5;    // 0..7 (m16 group within TQ=128)
    const int lane = tid & 31;
    const int g    = lane >> 2;
    const int tg   = lane & 3;

    const int q0 = blockIdx.x * BTQ;
    const int h  = blockIdx.y;
    const int b  = blockIdx.z;
    const size_t bh = (size_t)b * NH + h;

    float* eg = attn + (bh * NS + q0) * NS;
    const float* vg = g_vtf + bh * NS * ND;

    if (tid < 128) rinv_s[tid] = g_rinv[bh * NS + q0 + tid];

    // ---- prologue: tiles 0,1 (e + v), one cp group each ----
    for (int t = 0; t < 2; t++) {
        float* ed = ebuf + t * BTQ * EBS;
        float* vd = vbuf + t * BTK * VSS;
        for (int i = tid; i < BTQ * (BTK / 4); i += BNT) {
            int r = i >> 4, c = (i & 15) << 2;
            cp_async16(ed + r * EBS + c, eg + (size_t)r * NS + t * BTK + c);
        }
        for (int i = tid; i < BTK * 16; i += BNT) {
            int r = i >> 4, c = (i & 15) << 2;
            cp_async16(vd + r * VSS + c, vg + (size_t)(t * BTK + r) * ND + c);
        }
        CP_COMMIT();
    }
    CP_WAIT(1);
    __syncthreads();

    const int r_lo = wid * 16 + g;
    float acc[8][4];
    #pragma unroll
    for (int nt = 0; nt < 8; nt++)
        #pragma unroll
        for (int j = 0; j < 4; j++) acc[nt][j] = 0.0f;

    for (int vt = 0; vt < BNTILES; vt++) {
        if (vt < BNTILES - 1) { CP_WAIT(1); } else { CP_WAIT(0); }
        __syncthreads();

        const float* eb = ebuf + (vt & 1) * BTQ * EBS;
        const float* vb = vbuf + (vt & 1) * BTK * VSS;

        #pragma unroll
        for (int s = 0; s < 8; s++) {
            int kl = s * 8;
            uint32_t a0 = __float_as_uint(eb[r_lo * EBS + kl + tg]);
            uint32_t a1 = __float_as_uint(eb[(r_lo + 8) * EBS + kl + tg]);
            uint32_t a2 = __float_as_uint(eb[r_lo * EBS + kl + tg + 4]);
            uint32_t a3 = __float_as_uint(eb[(r_lo + 8) * EBS + kl + tg + 4]);
            #pragma unroll
            for (int nt = 0; nt < 8; nt++) {
                uint32_t b0 = __float_as_uint(vb[(kl + tg) * VSS + nt * 8 + g]);
                uint32_t b1 = __float_as_uint(vb[(kl + tg + 4) * VSS + nt * 8 + g]);
                mma_tf32(acc[nt], a0, a1, a2, a3, b0, b1);
            }
        }

        // normalize + write back attn chunk [BTQ x BTK]
        for (int i = tid; i < BTQ * (BTK / 4); i += BNT) {
            int row = i >> 4, c = (i & 15) << 2;
            float rv = rinv_s[row];
            float4 p = *(const float4*)(eb + row * EBS + c);
            p.x *= rv; p.y *= rv; p.z *= rv; p.w *= rv;
            __stcs((float4*)(eg + (size_t)row * NS + vt * BTK + c), p);
        }
        __syncthreads();

        if (vt + 2 < BNTILES) {
            float* ed = ebuf + (vt & 1) * BTQ * EBS;
            float* vd = vbuf + (vt & 1) * BTK * VSS;
            for (int i = tid; i < BTQ * (BTK / 4); i += BNT) {
                int r = i >> 4, c = (i & 15) << 2;
                cp_async16(ed + r * EBS + c, eg + (size_t)r * NS + (vt + 2) * BTK + c);
            }
            for (int i = tid; i < BTK * 16; i += BNT) {
                int r = i >> 4, c = (i & 15) << 2;
                cp_async16(vd + r * VSS + c, vg + (size_t)((vt + 2) * BTK + r) * ND + c);
            }
            CP_COMMIT();
        }
    }

    // ---- direct epilogue: each warp owns rows r_lo, r_lo+8 completely ----
    {
        float rv_lo = rinv_s[r_lo];
        float rv_hi = rinv_s[r_lo + 8];
        float* op_lo = out + (bh * NS + (size_t)(q0 + r_lo)) * ND;
        float* op_hi = out + (bh * NS + (size_t)(q0 + r_lo + 8)) * ND;
        #pragma unroll
        for (int nt = 0; nt < 8; nt++) {
            int col = nt * 8 + 2 * tg;
            *(float2*)(op_lo + col) = make_float2(acc[nt][0] * rv_lo, acc[nt][1] * rv_lo);
            *(float2*)(op_hi + col) = make_float2(acc[nt][2] * rv_hi, acc[nt][3] * rv_hi);
        }
    }
}

extern "C" void kernel_launch(void* const* d_in, const int* in_sizes, int n_in,
                              void* d_out, int out_size) {
    const float* q    = (const float*)d_in[0];
    const float* k    = (const float*)d_in[1];
    const float* v    = (const float*)d_in[2];
    const int*   mask = (const int*)  d_in[3];
    const float* adj  = (const float*)d_in[4];
    const float* dist = (const float*)d_in[5];

    float* out  = (float*)d_out;                      // [B,H,S,D]
    float* attn = out + (size_t)NB * NH * NS * ND;    // [B,H,S,S]

    prep_all_kernel<<<PREP_TBL_BLOCKS + PREP_QKV_BLOCKS, 256>>>(dist, adj, mask, q, k, v);

    const size_t smem_a = (size_t)(ATQ * QHS + 2 * ATK * KHS) * sizeof(float);
    cudaFuncSetAttribute(score_kernel,
                         cudaFuncAttributeMaxDynamicSharedMemorySize, (int)smem_a);
    dim3 gridA(NS / ATQ, NH, NB);
    score_kernel<<<gridA, ANT, smem_a>>>(attn);

    const size_t smem_b = (size_t)(2 * BTQ * EBS + 2 * BTK * VSS + 128) * sizeof(float);
    cudaFuncSetAttribute(pv_kernel,
                         cudaFuncAttributeMaxDynamicSharedMemorySize, (int)smem_b);
    dim3 gridB(NS / BTQ, NH, NB);
    pv_kernel<<<gridB, BNT, smem_b>>>(out, attn);
}